// round 1
// baseline (speedup 1.0000x reference)
#include <cuda_runtime.h>
#include <cstdint>
#include <cstddef>

// ---------------------------------------------------------------------------
// Problem shape (fixed by the dataset): data [S=1024, B=256, I=2],
// W_ih [256,2], b_ih [256], W_hh [256,256], b_hh [256], lin_W [2,256], lin_b[2]
// out = softmax_i( h_out[s,b,:] @ lin_W[i,:] + lin_b[i] ), h scan with tanh.
// ---------------------------------------------------------------------------

#define S_LEN    1024
#define BATCH    256
#define HID      256
#define HHALF    128     // output rows per CTA (cluster of 2 splits H)
#define BC       4       // batch rows per cluster
#define NTHREADS 256
#define WSTR     260     // padded row stride (floats) -> conflict-free LDS.128
#define HPROW    260
#define HPBUF    (BC*HPROW)

// shared memory layout (float offsets)
#define W_OFF    0
#define HP_OFF   (HHALF*WSTR)             // 33280
#define BIAS_OFF (HP_OFF + 2*HPBUF)       // 35360
#define WIH0_OFF (BIAS_OFF + HHALF)
#define WIH1_OFF (WIH0_OFF + HHALF)
#define X_OFF    (WIH1_OFF + HHALF)       // 35744 ; 2 bufs x 4 rows x 2
#define SMEM_FLOATS (X_OFF + 16)          // 35760
#define SMEM_BYTES  (SMEM_FLOATS * 4)     // 143040 B

// hidden-state scratch for the head kernel: [S][B][H] fp32 = 268 MB
__device__ float g_h[(size_t)S_LEN * BATCH * HID];

typedef unsigned long long u64;

// Packed fp32x2 FMA (Blackwell; 2 fp32 MACs per lane-instruction).
__device__ __forceinline__ void fma2(u64& acc, u64 a, u64 b) {
    asm("fma.rn.f32x2 %0, %1, %2, %0;" : "+l"(acc) : "l"(a), "l"(b));
}
__device__ __forceinline__ float pairsum(u64 v) {
    return __uint_as_float((unsigned)(v & 0xffffffffull)) +
           __uint_as_float((unsigned)(v >> 32));
}

// ---------------------------------------------------------------------------
// Scan kernel: 64 clusters x 2 CTAs. CTA rank r holds W_hh rows
// [r*128, r*128+128) in smem (fp32). Each cluster owns 4 batch rows.
// Thread t: hh = t>>1 (output row within half), bp = t&1 (batch pair).
// Per step: each thread does 2 batch rows x 256 k = 256 f32x2 FMAs.
// h halves exchanged via st.shared::cluster + barrier.cluster per step.
// ---------------------------------------------------------------------------
__global__ void __launch_bounds__(NTHREADS, 1) __cluster_dims__(2, 1, 1)
rnn_scan_kernel(const float* __restrict__ data,
                const float* __restrict__ W_ih,
                const float* __restrict__ b_ih,
                const float* __restrict__ W_hh,
                const float* __restrict__ b_hh)
{
    extern __shared__ float sm[];
    const int tid = threadIdx.x;
    uint32_t rank;
    asm("mov.u32 %0, %%cluster_ctarank;" : "=r"(rank));
    const int g   = blockIdx.x >> 1;        // batch group (4 rows)
    const int hh  = tid >> 1;
    const int bp  = tid & 1;
    const int r0  = 2 * bp, r1 = 2 * bp + 1;
    const int col = (int)rank * HHALF + hh; // global h column this thread owns

    // ---- one-time init: stage W half, biases, W_ih cols, h0=0, x0=[1,0] ----
    for (int i = tid; i < HHALF * 64; i += NTHREADS) {
        int r = i >> 6, c = (i & 63) << 2;
        float4 v = *(const float4*)(W_hh + ((size_t)((int)rank * HHALF + r)) * HID + c);
        *(float4*)(sm + W_OFF + r * WSTR + c) = v;
    }
    for (int i = tid; i < HPBUF; i += NTHREADS) sm[HP_OFF + i] = 0.0f;   // h buf 0
    if (tid < HHALF) {
        int hg = (int)rank * HHALF + tid;
        sm[BIAS_OFF + tid] = b_ih[hg] + b_hh[hg];
        sm[WIH0_OFF + tid] = W_ih[hg * 2 + 0];
        sm[WIH1_OFF + tid] = W_ih[hg * 2 + 1];
    }
    if (tid < 2 * BC) sm[X_OFF + tid] = (tid & 1) ? 0.0f : 1.0f;          // x[0]=[1,0]
    __syncthreads();

    uint32_t smem_base;
    asm("{ .reg .u64 t; cvta.to.shared.u64 t, %1; cvt.u32.u64 %0, t; }"
        : "=r"(smem_base) : "l"(sm));
    uint32_t peer_base;
    asm("mapa.shared::cluster.u32 %0, %1, %2;"
        : "=r"(peer_base) : "r"(smem_base), "r"(rank ^ 1u));

    const float biasv = sm[BIAS_OFF + hh];
    const float wih0v = sm[WIH0_OFF + hh];
    const float wih1v = sm[WIH1_OFF + hh];
    const float* wr = sm + W_OFF + hh * WSTR;

    for (int s = 0; s < S_LEN; ++s) {
        const int cur = s & 1, nxt = cur ^ 1;

        // prefetch x for step s+1 (x[s+1] = data[s]); landed into smem at step end
        float xreg = 0.0f;
        const bool havex = (tid < 2 * BC) && (s < S_LEN - 1);
        if (havex)
            xreg = data[(size_t)s * BATCH * 2 + (g * BC + (tid >> 1)) * 2 + (tid & 1)];

        const float* h0p = sm + HP_OFF + cur * HPBUF + r0 * HPROW;
        const float* h1p = sm + HP_OFF + cur * HPBUF + r1 * HPROW;
        u64 a0 = 0, a1 = 0, b0 = 0, b1 = 0;
        #pragma unroll 8
        for (int k = 0; k < HID; k += 4) {
            ulonglong2 w  = *(const ulonglong2*)(wr  + k);  // W[hh][k..k+3] (bcast pairs)
            ulonglong2 h0 = *(const ulonglong2*)(h0p + k);
            ulonglong2 h1 = *(const ulonglong2*)(h1p + k);
            fma2(a0, w.x, h0.x); fma2(a1, w.y, h0.y);
            fma2(b0, w.x, h1.x); fma2(b1, w.y, h1.y);
        }
        float s0 = pairsum(a0) + pairsum(a1);
        float s1 = pairsum(b0) + pairsum(b1);

        const float* xc = sm + X_OFF + cur * 8;
        float v0 = tanhf(fmaf(xc[r0 * 2 + 0], wih0v, fmaf(xc[r0 * 2 + 1], wih1v, biasv)) + s0);
        float v1 = tanhf(fmaf(xc[r1 * 2 + 0], wih0v, fmaf(xc[r1 * 2 + 1], wih1v, biasv)) + s1);

        // publish h_t: local half + peer half (DSMEM) + global scratch for head
        const int slot0 = HP_OFF + nxt * HPBUF + r0 * HPROW + col;
        const int slot1 = HP_OFF + nxt * HPBUF + r1 * HPROW + col;
        sm[slot0] = v0;
        sm[slot1] = v1;
        asm volatile("st.shared::cluster.f32 [%0], %1;"
                     :: "r"(peer_base + (uint32_t)slot0 * 4u), "f"(v0) : "memory");
        asm volatile("st.shared::cluster.f32 [%0], %1;"
                     :: "r"(peer_base + (uint32_t)slot1 * 4u), "f"(v1) : "memory");
        g_h[((size_t)s * BATCH + g * BC + r0) * HID + col] = v0;
        g_h[((size_t)s * BATCH + g * BC + r1) * HID + col] = v1;

        if (havex) sm[X_OFF + nxt * 8 + tid] = xreg;

        // release own writes (incl. DSMEM) / acquire peer's; also local sync
        asm volatile("barrier.cluster.arrive.aligned;" ::: "memory");
        asm volatile("barrier.cluster.wait.aligned;"   ::: "memory");
    }
}

// ---------------------------------------------------------------------------
// Head: logits = h @ lin_W^T + lin_b, softmax over I=2. One warp per (s,b).
// ---------------------------------------------------------------------------
__global__ void __launch_bounds__(256)
rnn_head_kernel(const float* __restrict__ lin_W,
                const float* __restrict__ lin_b,
                float* __restrict__ out)
{
    __shared__ float w0s[HID], w1s[HID], lbs[2];
    const int tid = threadIdx.x;
    if (tid < HID) { w0s[tid] = lin_W[tid]; w1s[tid] = lin_W[HID + tid]; }
    if (tid < 2)   lbs[tid] = lin_b[tid];
    __syncthreads();

    const int lane = tid & 31;
    const size_t sb = (size_t)blockIdx.x * 8 + (tid >> 5);
    const float* hp = g_h + sb * HID;

    float4 h0 = *(const float4*)(hp + lane * 4);
    float4 h1 = *(const float4*)(hp + 128 + lane * 4);
    float4 wa0 = *(const float4*)(w0s + lane * 4);
    float4 wa1 = *(const float4*)(w0s + 128 + lane * 4);
    float4 wb0 = *(const float4*)(w1s + lane * 4);
    float4 wb1 = *(const float4*)(w1s + 128 + lane * 4);

    float acc0 = h0.x*wa0.x + h0.y*wa0.y + h0.z*wa0.z + h0.w*wa0.w
               + h1.x*wa1.x + h1.y*wa1.y + h1.z*wa1.z + h1.w*wa1.w;
    float acc1 = h0.x*wb0.x + h0.y*wb0.y + h0.z*wb0.z + h0.w*wb0.w
               + h1.x*wb1.x + h1.y*wb1.y + h1.z*wb1.z + h1.w*wb1.w;

    #pragma unroll
    for (int m = 16; m; m >>= 1) {
        acc0 += __shfl_xor_sync(0xffffffffu, acc0, m);
        acc1 += __shfl_xor_sync(0xffffffffu, acc1, m);
    }
    if (lane == 0) {
        float l0 = acc0 + lbs[0], l1 = acc1 + lbs[1];
        float mx = fmaxf(l0, l1);
        float e0 = expf(l0 - mx), e1 = expf(l1 - mx);
        float inv = 1.0f / (e0 + e1);
        float2 o; o.x = e0 * inv; o.y = e1 * inv;
        *(float2*)(out + sb * 2) = o;
    }
}

// ---------------------------------------------------------------------------
extern "C" void kernel_launch(void* const* d_in, const int* in_sizes, int n_in,
                              void* d_out, int out_size)
{
    (void)in_sizes; (void)n_in; (void)out_size;
    const float* data  = (const float*)d_in[0];
    const float* W_ih  = (const float*)d_in[1];
    const float* b_ih  = (const float*)d_in[2];
    const float* W_hh  = (const float*)d_in[3];
    const float* b_hh  = (const float*)d_in[4];
    const float* lin_W = (const float*)d_in[5];
    const float* lin_b = (const float*)d_in[6];
    float* out = (float*)d_out;

    cudaFuncSetAttribute(rnn_scan_kernel,
                         cudaFuncAttributeMaxDynamicSharedMemorySize, SMEM_BYTES);

    // 64 clusters x 2 CTAs; __cluster_dims__ makes the plain launch a cluster launch
    rnn_scan_kernel<<<128, NTHREADS, SMEM_BYTES>>>(data, W_ih, b_ih, W_hh, b_hh);

    // 262144 (s,b) pairs, one warp each, 8 warps per block
    rnn_head_kernel<<<(S_LEN * BATCH) / 8, 256>>>(lin_W, lin_b, out);
}

// round 2
// speedup vs baseline: 1.2314x; 1.2314x over previous
#include <cuda_runtime.h>
#include <cstdint>
#include <cstddef>

// ---------------------------------------------------------------------------
// data [S=1024, B=256, I=2], W_ih [256,2], b_ih[256], W_hh [256,256],
// b_hh[256], lin_W [2,256], lin_b[2]; out = softmax(h @ lin_W^T + lin_b).
//
// Scan: 64 clusters x 2 CTAs x 256 thr. CTA rank r owns output cols
// [r*128, r*128+128). Thread (hh = tid>>1, kc = tid&1) keeps
// W_hh[col][kc*128 .. +127] in 64 u64 REGISTERS (fp32x2 pairs).
// Per step: 4 batch rows x 128 k per thread (fma.rn.f32x2), shfl pair
// reduction, even lane finalizes rows 0-1, odd lane rows 2-3.
// h exchanged through smem (local) + st.shared::cluster (peer half).
// ---------------------------------------------------------------------------

#define S_LEN    1024
#define BATCH    256
#define HID      256
#define BC       4
#define NTHREADS 256

#define HROW     264              // 128 | pad4 | 128 | pad4  (264 % 32 == 8)
#define HPBUF    (BC*HROW)        // 1056
#define HP_OFF   0
#define X_OFF    (2*HPBUF)        // 2112 ; 2 bufs x 8 floats
#define SMEM_FLOATS (X_OFF + 16)  // 2128 floats = 8512 B (static smem)

__device__ float g_h[(size_t)S_LEN * BATCH * HID];   // 268 MB scratch

typedef unsigned long long u64;

__device__ __forceinline__ void fma2(u64& acc, u64 a, u64 b) {
    asm("fma.rn.f32x2 %0, %1, %2, %0;" : "+l"(acc) : "l"(a), "l"(b));
}
__device__ __forceinline__ u64 add2(u64 a, u64 b) {
    u64 r; asm("add.rn.f32x2 %0, %1, %2;" : "=l"(r) : "l"(a), "l"(b)); return r;
}
__device__ __forceinline__ float pairsum(u64 v) {
    return __uint_as_float((unsigned)(v & 0xffffffffull)) +
           __uint_as_float((unsigned)(v >> 32));
}
__device__ __forceinline__ float fast_tanh(float x) {
    float e = __expf(-2.0f * x);
    return __fdividef(1.0f - e, 1.0f + e);
}

__global__ void __launch_bounds__(NTHREADS, 1) __cluster_dims__(2, 1, 1)
rnn_scan_kernel(const float* __restrict__ data,
                const float* __restrict__ W_ih,
                const float* __restrict__ b_ih,
                const float* __restrict__ W_hh,
                const float* __restrict__ b_hh)
{
    __shared__ float sm[SMEM_FLOATS];
    const int tid = threadIdx.x;
    uint32_t rank;
    asm("mov.u32 %0, %%cluster_ctarank;" : "=r"(rank));
    const int g   = blockIdx.x >> 1;          // batch group of 4 rows
    const int hh  = tid >> 1;                 // output row within half
    const int kc  = tid & 1;                  // k-half this thread reduces
    const int col = (int)rank * 128 + hh;     // global output column
    const int rA  = kc * 2, rB = kc * 2 + 1;  // batch rows this lane finalizes

    // ---- init: zero h buf0, x0 = [1,0] ----
    for (int i = tid; i < HPBUF; i += NTHREADS) sm[HP_OFF + i] = 0.0f;
    if (tid < 2 * BC) sm[X_OFF + tid] = (tid & 1) ? 0.0f : 1.0f;

    // ---- W_hh half-row -> 64 u64 registers ----
    u64 W[64];
    {
        const float* wp = W_hh + (size_t)col * HID + kc * 128;
        #pragma unroll
        for (int j = 0; j < 32; ++j) {
            ulonglong2 t = *(const ulonglong2*)(wp + 4 * j);
            W[2 * j] = t.x; W[2 * j + 1] = t.y;
        }
    }
    const float biasv = b_ih[col] + b_hh[col];
    const float wih0  = W_ih[col * 2 + 0];
    const float wih1  = W_ih[col * 2 + 1];
    __syncthreads();

    uint32_t smem_base;
    asm("{ .reg .u64 t; cvta.to.shared.u64 t, %1; cvt.u32.u64 %0, t; }"
        : "=r"(smem_base) : "l"(sm));
    uint32_t peer_base;
    asm("mapa.shared::cluster.u32 %0, %1, %2;"
        : "=r"(peer_base) : "r"(smem_base), "r"(rank ^ 1u));

    // column slot inside an h row (4-float pad between the halves)
    const int colp = (int)rank * 132 + hh;

    for (int s = 0; s < S_LEN; ++s) {
        const int cur = s & 1, nxt = cur ^ 1;

        // prefetch x for step s+1 (x[s+1] = data[s])
        float xreg = 0.0f;
        const bool havex = (tid < 2 * BC) && (s < S_LEN - 1);
        if (havex)
            xreg = data[(size_t)s * BATCH * 2 + (g * BC + (tid >> 1)) * 2 + (tid & 1)];

        // ---- matvec partials: 4 rows x 128 k, W in regs, h broadcast LDS ----
        const float* hb = sm + HP_OFF + cur * HPBUF + kc * 132;
        u64 a0 = 0, a1 = 0, a2 = 0, a3 = 0, a4 = 0, a5 = 0, a6 = 0, a7 = 0;
        #pragma unroll
        for (int j = 0; j < 32; ++j) {
            const int k = 4 * j;
            ulonglong2 h0 = *(const ulonglong2*)(hb + 0 * HROW + k);
            ulonglong2 h1 = *(const ulonglong2*)(hb + 1 * HROW + k);
            ulonglong2 h2 = *(const ulonglong2*)(hb + 2 * HROW + k);
            ulonglong2 h3 = *(const ulonglong2*)(hb + 3 * HROW + k);
            fma2(a0, W[2*j], h0.x); fma2(a1, W[2*j+1], h0.y);
            fma2(a2, W[2*j], h1.x); fma2(a3, W[2*j+1], h1.y);
            fma2(a4, W[2*j], h2.x); fma2(a5, W[2*j+1], h2.y);
            fma2(a6, W[2*j], h3.x); fma2(a7, W[2*j+1], h3.y);
        }
        float p0 = pairsum(add2(a0, a1));
        float p1 = pairsum(add2(a2, a3));
        float p2 = pairsum(add2(a4, a5));
        float p3 = pairsum(add2(a6, a7));

        // pair reduction across the two k-halves (partner = lane^1)
        float q0 = __shfl_xor_sync(0xffffffffu, p0, 1);
        float q1 = __shfl_xor_sync(0xffffffffu, p1, 1);
        float q2 = __shfl_xor_sync(0xffffffffu, p2, 1);
        float q3 = __shfl_xor_sync(0xffffffffu, p3, 1);
        float tA = (kc == 0) ? (p0 + q0) : (p2 + q2);
        float tB = (kc == 0) ? (p1 + q1) : (p3 + q3);

        const float* xc = sm + X_OFF + cur * 8;
        float preA = fmaf(xc[rA * 2], wih0, fmaf(xc[rA * 2 + 1], wih1, biasv)) + tA;
        float preB = fmaf(xc[rB * 2], wih0, fmaf(xc[rB * 2 + 1], wih1, biasv)) + tB;
        float vA = fast_tanh(preA);
        float vB = fast_tanh(preB);

        // ---- publish h_t: peer (DSMEM) first to start the flight early ----
        const int slotA = HP_OFF + nxt * HPBUF + rA * HROW + colp;
        const int slotB = HP_OFF + nxt * HPBUF + rB * HROW + colp;
        asm volatile("st.shared::cluster.f32 [%0], %1;"
                     :: "r"(peer_base + (uint32_t)slotA * 4u), "f"(vA) : "memory");
        asm volatile("st.shared::cluster.f32 [%0], %1;"
                     :: "r"(peer_base + (uint32_t)slotB * 4u), "f"(vB) : "memory");
        sm[slotA] = vA;
        sm[slotB] = vB;
        g_h[((size_t)s * BATCH + g * BC + rA) * HID + col] = vA;
        g_h[((size_t)s * BATCH + g * BC + rB) * HID + col] = vB;

        if (havex) sm[X_OFF + nxt * 8 + tid] = xreg;

        asm volatile("barrier.cluster.arrive.aligned;" ::: "memory");
        asm volatile("barrier.cluster.wait.aligned;"   ::: "memory");
    }
}

// ---------------------------------------------------------------------------
// Head: logits = h @ lin_W^T + lin_b, softmax over I=2. One warp per (s,b).
// ---------------------------------------------------------------------------
__global__ void __launch_bounds__(256)
rnn_head_kernel(const float* __restrict__ lin_W,
                const float* __restrict__ lin_b,
                float* __restrict__ out)
{
    __shared__ float w0s[HID], w1s[HID], lbs[2];
    const int tid = threadIdx.x;
    if (tid < HID) { w0s[tid] = lin_W[tid]; w1s[tid] = lin_W[HID + tid]; }
    if (tid < 2)   lbs[tid] = lin_b[tid];
    __syncthreads();

    const int lane = tid & 31;
    const size_t sb = (size_t)blockIdx.x * 8 + (tid >> 5);
    const float* hp = g_h + sb * HID;

    float4 h0 = *(const float4*)(hp + lane * 4);
    float4 h1 = *(const float4*)(hp + 128 + lane * 4);
    float4 wa0 = *(const float4*)(w0s + lane * 4);
    float4 wa1 = *(const float4*)(w0s + 128 + lane * 4);
    float4 wb0 = *(const float4*)(w1s + lane * 4);
    float4 wb1 = *(const float4*)(w1s + 128 + lane * 4);

    float acc0 = h0.x*wa0.x + h0.y*wa0.y + h0.z*wa0.z + h0.w*wa0.w
               + h1.x*wa1.x + h1.y*wa1.y + h1.z*wa1.z + h1.w*wa1.w;
    float acc1 = h0.x*wb0.x + h0.y*wb0.y + h0.z*wb0.z + h0.w*wb0.w
               + h1.x*wb1.x + h1.y*wb1.y + h1.z*wb1.z + h1.w*wb1.w;

    #pragma unroll
    for (int m = 16; m; m >>= 1) {
        acc0 += __shfl_xor_sync(0xffffffffu, acc0, m);
        acc1 += __shfl_xor_sync(0xffffffffu, acc1, m);
    }
    if (lane == 0) {
        float l0 = acc0 + lbs[0], l1 = acc1 + lbs[1];
        float mx = fmaxf(l0, l1);
        float e0 = expf(l0 - mx), e1 = expf(l1 - mx);
        float inv = 1.0f / (e0 + e1);
        float2 o; o.x = e0 * inv; o.y = e1 * inv;
        *(float2*)(out + sb * 2) = o;
    }
}

// ---------------------------------------------------------------------------
extern "C" void kernel_launch(void* const* d_in, const int* in_sizes, int n_in,
                              void* d_out, int out_size)
{
    (void)in_sizes; (void)n_in; (void)out_size;
    const float* data  = (const float*)d_in[0];
    const float* W_ih  = (const float*)d_in[1];
    const float* b_ih  = (const float*)d_in[2];
    const float* W_hh  = (const float*)d_in[3];
    const float* b_hh  = (const float*)d_in[4];
    const float* lin_W = (const float*)d_in[5];
    const float* lin_b = (const float*)d_in[6];
    float* out = (float*)d_out;

    rnn_scan_kernel<<<128, NTHREADS>>>(data, W_ih, b_ih, W_hh, b_hh);
    rnn_head_kernel<<<(S_LEN * BATCH) / 8, 256>>>(lin_W, lin_b, out);
}

// round 3
// speedup vs baseline: 1.3332x; 1.0827x over previous
#include <cuda_runtime.h>
#include <cuda_fp16.h>
#include <cstdint>
#include <cstddef>

// ---------------------------------------------------------------------------
// data [S=1024, B=256, I=2], W_ih [256,2], b_ih[256], W_hh [256,256],
// b_hh[256], lin_W [2,256], lin_b[2]; out = softmax(h @ lin_W^T + lin_b).
//
// 64 clusters x 2 CTAs x 256 thr. CTA rank r owns h cols [r*128, r*128+128).
// Warp-level k split: warps 0-3 -> k-half 0, warps 4-7 -> k-half 1.
// Thread (kc, c): col = rank*128 + c, W_hh[col][kc*128..+127] in 64 u64 regs.
// Warps whose k-half == rank consume LOCALLY produced h (just __syncthreads);
// the other warps sleep on an mbarrier fed by the peer's DSMEM stores, so the
// cluster exchange latency hides under the local warps' FMA stream.
// Partials for the two k-halves meet via a smem psum exchange.
// ---------------------------------------------------------------------------

#define S_LEN    1024
#define BATCH    256
#define HID      256
#define NTHREADS 256

#define HROW   264                  // 128 | pad4 | 128 | pad4
#define HPBUF  (4*HROW)             // 1056 floats (4 batch rows)
#define HP_OFF 0
#define X_OFF  (2*HPBUF)            // 2112 : 2 bufs x 4 rows x 2
#define PS_OFF (X_OFF + 16)         // 2128 : psum[2][128][4]
#define SMEM_FLOATS (PS_OFF + 1024) // 3152 floats = 12608 B

__device__ __half g_h[(size_t)S_LEN * BATCH * HID];   // 134 MB fp16 scratch

typedef unsigned long long u64;

__device__ __forceinline__ void fma2(u64& acc, u64 a, u64 b) {
    asm("fma.rn.f32x2 %0, %1, %2, %0;" : "+l"(acc) : "l"(a), "l"(b));
}
__device__ __forceinline__ u64 add2(u64 a, u64 b) {
    u64 r; asm("add.rn.f32x2 %0, %1, %2;" : "=l"(r) : "l"(a), "l"(b)); return r;
}
__device__ __forceinline__ float pairsum(u64 v) {
    return __uint_as_float((unsigned)(v & 0xffffffffull)) +
           __uint_as_float((unsigned)(v >> 32));
}
__device__ __forceinline__ float fast_tanh(float x) {
    float e = __expf(-2.0f * x);
    return __fdividef(1.0f - e, 1.0f + e);
}

__global__ void __launch_bounds__(NTHREADS, 1) __cluster_dims__(2, 1, 1)
rnn_scan_kernel(const float* __restrict__ data,
                const float* __restrict__ W_ih,
                const float* __restrict__ b_ih,
                const float* __restrict__ W_hh,
                const float* __restrict__ b_hh)
{
    __shared__ __align__(16) float sm[SMEM_FLOATS];
    __shared__ __align__(8)  unsigned long long mb[2];

    const int tid  = threadIdx.x;
    uint32_t rank;
    asm("mov.u32 %0, %%cluster_ctarank;" : "=r"(rank));
    const int g    = blockIdx.x >> 1;           // batch group of 4 rows
    const int wid  = tid >> 5;
    const int lane = tid & 31;
    const int kc   = wid >> 2;                  // k-half this warp reduces
    const int c    = (wid & 3) * 32 + lane;     // local col 0..127
    const int col  = (int)rank * 128 + c;       // global output column
    const bool isLocal = (kc == (int)rank);     // consumes locally-made half?
    const int rA = 2 * kc, rB = 2 * kc + 1;     // batch rows this thread finals

    // ---- init: zero h buf0, x buf0 = [1,0] x 4 rows ----
    for (int i = tid; i < HPBUF; i += NTHREADS) sm[HP_OFF + i] = 0.0f;
    if (tid < 8) sm[X_OFF + tid] = (tid & 1) ? 0.0f : 1.0f;

    // ---- W_hh half-row -> 64 u64 registers ----
    u64 W[64];
    {
        const float* wp = W_hh + (size_t)col * HID + kc * 128;
        #pragma unroll
        for (int j = 0; j < 32; ++j) {
            ulonglong2 t = *(const ulonglong2*)(wp + 4 * j);
            W[2 * j] = t.x; W[2 * j + 1] = t.y;
        }
    }
    const float biasv = b_ih[col] + b_hh[col];
    const float wih0  = W_ih[col * 2 + 0];
    const float wih1  = W_ih[col * 2 + 1];

    uint32_t sm_u32, mb_u32;
    asm("{ .reg .u64 t; cvta.to.shared.u64 t, %1; cvt.u32.u64 %0, t; }"
        : "=r"(sm_u32) : "l"(sm));
    asm("{ .reg .u64 t; cvta.to.shared.u64 t, %1; cvt.u32.u64 %0, t; }"
        : "=r"(mb_u32) : "l"(mb));
    uint32_t peer_sm, peer_mb;
    asm("mapa.shared::cluster.u32 %0, %1, %2;"
        : "=r"(peer_sm) : "r"(sm_u32), "r"(rank ^ 1u));
    asm("mapa.shared::cluster.u32 %0, %1, %2;"
        : "=r"(peer_mb) : "r"(mb_u32), "r"(rank ^ 1u));

    if (tid == 0) {
        asm volatile("mbarrier.init.shared.b64 [%0], %1;" :: "r"(mb_u32),     "r"(256u) : "memory");
        asm volatile("mbarrier.init.shared.b64 [%0], %1;" :: "r"(mb_u32 + 8), "r"(256u) : "memory");
    }
    __syncthreads();
    // peer mbars must be live before any arrive lands there
    asm volatile("barrier.cluster.arrive.aligned;" ::: "memory");
    asm volatile("barrier.cluster.wait.aligned;"   ::: "memory");

    for (int s = 0; s < S_LEN; ++s) {
        const int cur = s & 1, nxt = cur ^ 1;

        // prefetch x for step s+1 (x[s+1] = data[s]) — independent load
        float xreg = 0.0f;
        const bool havex = (tid < 8) && (s < S_LEN - 1);
        if (havex)
            xreg = data[(size_t)s * BATCH * 2 + (g * 4 + (tid >> 1)) * 2 + (tid & 1)];

        // remote-half warps: sleep until peer's DSMEM stores for buf[cur] land
        if (s > 0 && !isLocal) {
            uint32_t par = (uint32_t)(((s >> 1) + (cur ^ 1)) & 1);
            uint32_t mba = mb_u32 + (uint32_t)cur * 8u;
            asm volatile(
                "{\n\t.reg .pred P;\n"
                "WL_%=:\n\t"
                "mbarrier.try_wait.parity.acquire.cluster.shared::cta.b64 P, [%0], %1, 0x989680;\n\t"
                "@P bra.uni WD_%=;\n\t"
                "bra.uni WL_%=;\n"
                "WD_%=:\n\t}"
                :: "r"(mba), "r"(par) : "memory");
        }

        // ---- matvec partials: 4 rows x 128 k on this warp's k-half.
        // All 32 lanes read the SAME h addresses -> pure LDS broadcast.
        const float* hb = sm + HP_OFF + cur * HPBUF + kc * 132;
        u64 a0 = 0, a1 = 0, a2 = 0, a3 = 0, a4 = 0, a5 = 0, a6 = 0, a7 = 0;
        #pragma unroll
        for (int j = 0; j < 32; ++j) {
            const int k = 4 * j;
            ulonglong2 h0 = *(const ulonglong2*)(hb + 0 * HROW + k);
            ulonglong2 h1 = *(const ulonglong2*)(hb + 1 * HROW + k);
            ulonglong2 h2 = *(const ulonglong2*)(hb + 2 * HROW + k);
            ulonglong2 h3 = *(const ulonglong2*)(hb + 3 * HROW + k);
            fma2(a0, W[2*j], h0.x); fma2(a1, W[2*j+1], h0.y);
            fma2(a2, W[2*j], h1.x); fma2(a3, W[2*j+1], h1.y);
            fma2(a4, W[2*j], h2.x); fma2(a5, W[2*j+1], h2.y);
            fma2(a6, W[2*j], h3.x); fma2(a7, W[2*j+1], h3.y);
        }
        float p0 = pairsum(add2(a0, a1));
        float p1 = pairsum(add2(a2, a3));
        float p2 = pairsum(add2(a4, a5));
        float p3 = pairsum(add2(a6, a7));

        // ---- cross-k-half partial exchange via smem ----
        float4 mine; mine.x = p0; mine.y = p1; mine.z = p2; mine.w = p3;
        *(float4*)(sm + PS_OFF + (size_t)(kc * 128 + c) * 4) = mine;
        __syncthreads();
        const float* pp = sm + PS_OFF + (size_t)((kc ^ 1) * 128 + c) * 4;
        float sumA = (kc ? p2 : p0) + pp[rA];
        float sumB = (kc ? p3 : p1) + pp[rB];

        const float* xc = sm + X_OFF + cur * 8;
        float vA = fast_tanh(fmaf(xc[rA*2], wih0, fmaf(xc[rA*2+1], wih1, biasv)) + sumA);
        float vB = fast_tanh(fmaf(xc[rB*2], wih0, fmaf(xc[rB*2+1], wih1, biasv)) + sumB);

        // ---- publish h_t ----
        const uint32_t slotA = (uint32_t)(HP_OFF + nxt * HPBUF + rA * HROW + (int)rank * 132 + c);
        const uint32_t slotB = (uint32_t)(HP_OFF + nxt * HPBUF + rB * HROW + (int)rank * 132 + c);
        asm volatile("st.shared::cluster.f32 [%0], %1;"
                     :: "r"(peer_sm + slotA * 4u), "f"(vA) : "memory");
        asm volatile("st.shared::cluster.f32 [%0], %1;"
                     :: "r"(peer_sm + slotB * 4u), "f"(vB) : "memory");
        sm[slotA] = vA;
        sm[slotB] = vB;
        g_h[((size_t)s * BATCH + g * 4 + rA) * HID + col] = __float2half(vA);
        g_h[((size_t)s * BATCH + g * 4 + rB) * HID + col] = __float2half(vB);
        if (havex) sm[X_OFF + nxt * 8 + tid] = xreg;

        // signal peer: my half of h_t is in its buf[nxt] (release orders the
        // st.shared::cluster data stores before the arrive)
        asm volatile("mbarrier.arrive.release.cluster.shared::cluster.b64 _, [%0];"
                     :: "r"(peer_mb + (uint32_t)nxt * 8u) : "memory");
        __syncthreads();   // local h + x visible to local warps next step
    }

    // keep smem/mbars alive until peer's trailing DSMEM traffic drains
    asm volatile("barrier.cluster.arrive.aligned;" ::: "memory");
    asm volatile("barrier.cluster.wait.aligned;"   ::: "memory");
}

// ---------------------------------------------------------------------------
// Head: logits = h @ lin_W^T + lin_b, softmax over I=2. One warp per (s,b).
// g_h is fp16 -> half the DRAM traffic of R2.
// ---------------------------------------------------------------------------
__global__ void __launch_bounds__(256)
rnn_head_kernel(const float* __restrict__ lin_W,
                const float* __restrict__ lin_b,
                float* __restrict__ out)
{
    __shared__ float w0s[HID], w1s[HID], lbs[2];
    const int tid = threadIdx.x;
    if (tid < HID) { w0s[tid] = lin_W[tid]; w1s[tid] = lin_W[HID + tid]; }
    if (tid < 2)   lbs[tid] = lin_b[tid];
    __syncthreads();

    const int lane = tid & 31;
    const size_t sb = (size_t)blockIdx.x * 8 + (tid >> 5);
    const __half* hp = g_h + sb * HID;

    // cols lane*4..+3 and 128+lane*4..+3 (4 halfs = 8B each)
    uint2 ra = *(const uint2*)(hp + lane * 4);
    uint2 rb = *(const uint2*)(hp + 128 + lane * 4);
    float2 fa0 = __half22float2(*(const __half2*)&ra.x);
    float2 fa1 = __half22float2(*(const __half2*)&ra.y);
    float2 fb0 = __half22float2(*(const __half2*)&rb.x);
    float2 fb1 = __half22float2(*(const __half2*)&rb.y);

    float4 wa0 = *(const float4*)(w0s + lane * 4);
    float4 wa1 = *(const float4*)(w0s + 128 + lane * 4);
    float4 wb0 = *(const float4*)(w1s + lane * 4);
    float4 wb1 = *(const float4*)(w1s + 128 + lane * 4);

    float acc0 = fa0.x*wa0.x + fa0.y*wa0.y + fa1.x*wa0.z + fa1.y*wa0.w
               + fb0.x*wa1.x + fb0.y*wa1.y + fb1.x*wa1.z + fb1.y*wa1.w;
    float acc1 = fa0.x*wb0.x + fa0.y*wb0.y + fa1.x*wb0.z + fa1.y*wb0.w
               + fb0.x*wb1.x + fb0.y*wb1.y + fb1.x*wb1.z + fb1.y*wb1.w;

    #pragma unroll
    for (int m = 16; m; m >>= 1) {
        acc0 += __shfl_xor_sync(0xffffffffu, acc0, m);
        acc1 += __shfl_xor_sync(0xffffffffu, acc1, m);
    }
    if (lane == 0) {
        float l0 = acc0 + lbs[0], l1 = acc1 + lbs[1];
        float mx = fmaxf(l0, l1);
        float e0 = expf(l0 - mx), e1 = expf(l1 - mx);
        float inv = 1.0f / (e0 + e1);
        float2 o; o.x = e0 * inv; o.y = e1 * inv;
        *(float2*)(out + sb * 2) = o;
    }
}

// ---------------------------------------------------------------------------
extern "C" void kernel_launch(void* const* d_in, const int* in_sizes, int n_in,
                              void* d_out, int out_size)
{
    (void)in_sizes; (void)n_in; (void)out_size;
    const float* data  = (const float*)d_in[0];
    const float* W_ih  = (const float*)d_in[1];
    const float* b_ih  = (const float*)d_in[2];
    const float* W_hh  = (const float*)d_in[3];
    const float* b_hh  = (const float*)d_in[4];
    const float* lin_W = (const float*)d_in[5];
    const float* lin_b = (const float*)d_in[6];
    float* out = (float*)d_out;

    rnn_scan_kernel<<<128, NTHREADS>>>(data, W_ih, b_ih, W_hh, b_hh);
    rnn_head_kernel<<<(S_LEN * BATCH) / 8, 256>>>(lin_W, lin_b, out);
}